// round 11
// baseline (speedup 1.0000x reference)
#include <cuda_runtime.h>
#include <cuda_bf16.h>

#define N_PART 1000000
#define N_GRID 128
#define N_NODES (N_GRID * N_GRID)
#define NREP 32

// Grid scratch (device globals — no allocation allowed; zero-initialized at load)
__device__ __align__(16) float4 g_node[NREP][N_NODES];  // (momx, momy, mass, pad)
__device__ __align__(16) float4 g_pair[N_NODES];        // {v[n].x, v[n].y, v[n+1].x, v[n+1].y}

__global__ void __launch_bounds__(256) k_p2g(
    const float2* __restrict__ x, const float2* __restrict__ v,
    const float4* __restrict__ C, const float4* __restrict__ F,
    const int* __restrict__ material, const float* __restrict__ Jp,
    float* __restrict__ out)
{
    int p = blockIdx.x * blockDim.x + threadIdx.x;
    if (p >= N_PART) return;
    float4* __restrict__ rep = g_node[blockIdx.x & (NREP - 1)];

    const float DT = 1e-4f;
    const float INV_DX = 128.0f;
    const float DX = 1.0f / 128.0f;
    const float P_MASS = 1.52587890625e-05f;
    const float MU_0 = 1000.0f / (2.0f * 1.2f);
    const float LAM_0 = 1000.0f * 0.2f / (1.2f * 0.6f);

    float2 xp = x[p];
    float2 vp = v[p];
    float4 c = C[p];
    float4 f = F[p];
    int m = material[p];
    float jp = Jp[p];

    // F = F + DT * (C @ F)
    float f00 = f.x + DT * (c.x * f.x + c.y * f.z);
    float f01 = f.y + DT * (c.x * f.y + c.y * f.w);
    float f10 = f.z + DT * (c.z * f.x + c.w * f.z);
    float f11 = f.w + DT * (c.z * f.y + c.w * f.w);

    float h = (m == 1) ? 0.3f : expf(10.0f * (1.0f - jp));
    float mu = (m == 0) ? 0.0f : MU_0 * h;
    float lam = LAM_0 * h;

    // Singular values (algebraic)
    float E  = 0.5f * (f00 + f11);
    float Fm = 0.5f * (f00 - f11);
    float G  = 0.5f * (f10 + f01);
    float H  = 0.5f * (f10 - f01);
    float q2 = E * E + H * H;
    float invQ = rsqrtf(fmaxf(q2, 1e-30f));
    float Q  = q2 * invQ;
    float Rr = sqrtf(Fm * Fm + G * G);
    float sx = Q + Rr;
    float sy = Q - Rr;

    // Polar rotation R = U Vh (trig-free)
    float rc = E * invQ;
    float rs = H * invQ;
    float r00 = rc, r01 = -rs, r10 = rs, r11 = rc;

    float clx = fminf(fmaxf(sx, 0.975f), 1.0045f);
    float cly = fminf(fmaxf(sy, 0.975f), 1.0045f);
    float J;
    if (m == 2) {
        jp *= (sx * sy) / (clx * cly);
        J = clx * cly;
        // F_snow = F @ (V diag(clx/sx, cly/sy) V^T)
        float k00 = f00 * f00 + f10 * f10;
        float k11 = f01 * f01 + f11 * f11;
        float k01 = f00 * f01 + f10 * f11;
        float d  = 0.5f * (k00 - k11);
        float rr2 = d * d + k01 * k01;
        float invr = (rr2 > 1e-24f) ? rsqrtf(rr2) : 0.0f;
        float c2 = d * invr;
        float s2 = k01 * invr;
        float rr0 = clx / sx;
        float rr1 = cly / sy;
        float avg = 0.5f * (rr0 + rr1);
        float dif = 0.5f * (rr0 - rr1);
        float m00 = avg + c2 * dif;
        float m11 = avg - c2 * dif;
        float m01 = s2 * dif;
        float nf00 = f00 * m00 + f01 * m01;
        float nf01 = f00 * m01 + f01 * m11;
        float nf10 = f10 * m00 + f11 * m01;
        float nf11 = f10 * m01 + f11 * m11;
        f00 = nf00; f01 = nf01; f10 = nf10; f11 = nf11;
    } else {
        J = sx * sy;
        if (m == 0) {
            float sj = sqrtf(J);
            f00 = sj; f01 = 0.f; f10 = 0.f; f11 = sj;
        }
    }

    // stress = -DT * (2*mu*(F-R)@F^T + I*lam*J*(J-1))
    float d00 = f00 - r00, d01 = f01 - r01;
    float d10 = f10 - r10, d11 = f11 - r11;
    float tm = 2.0f * mu;
    float diag = lam * J * (J - 1.0f);
    float s00 = tm * (d00 * f00 + d01 * f01) + diag;
    float s01 = tm * (d00 * f10 + d01 * f11);
    float s10 = tm * (d10 * f00 + d11 * f01);
    float s11 = tm * (d10 * f10 + d11 * f11) + diag;
    const float scale = -1e-4f;  // -DT
    float a00 = scale * s00 + P_MASS * c.x;
    float a01 = scale * s01 + P_MASS * c.y;
    float a10 = scale * s10 + P_MASS * c.z;
    float a11 = scale * s11 + P_MASS * c.w;

    float momx = P_MASS * vp.x - (a00 * xp.x + a01 * xp.y);
    float momy = P_MASS * vp.y - (a10 * xp.x + a11 * xp.y);

    float bxf = floorf(xp.x * INV_DX - 0.5f);
    float byf = floorf(xp.y * INV_DX - 0.5f);
    int bx = (int)bxf, by = (int)byf;
    float fxx = xp.x * INV_DX - bxf;
    float fxy = xp.y * INV_DX - byf;
    float wx[3], wy[3];
    wx[0] = 0.5f * (1.5f - fxx) * (1.5f - fxx);
    wx[1] = 0.75f - (fxx - 1.0f) * (fxx - 1.0f);
    wx[2] = 0.5f * (fxx - 0.5f) * (fxx - 0.5f);
    wy[0] = 0.5f * (1.5f - fxy) * (1.5f - fxy);
    wy[1] = 0.75f - (fxy - 1.0f) * (fxy - 1.0f);
    wy[2] = 0.5f * (fxy - 0.5f) * (fxy - 0.5f);

    // Fold affine into momentum: contrib = wt * (mom + A @ node_pos)
    #pragma unroll
    for (int i = 0; i < 3; i++) {
        float nodex = (float)(bx + i) * DX;
        float axx = a00 * nodex;
        float ayx = a10 * nodex;
        int rowbase = (bx + i) * N_GRID;
        #pragma unroll
        for (int j = 0; j < 3; j++) {
            float nodey = (float)(by + j) * DX;
            float wt = wx[i] * wy[j];
            int idx = rowbase + by + j;
            float cx = wt * (momx + axx + a01 * nodey);
            float cy = wt * (momy + ayx + a11 * nodey);
            atomicAdd(&rep[idx], make_float4(cx, cy, wt * P_MASS, 0.f));
        }
    }

    // Outputs (streaming stores — keep L2 for the atomic working set)
    __stcs((float4*)(out + 8000000) + p, make_float4(f00, f01, f10, f11));
    __stcs(out + 12000000 + p, (float)m);
    __stcs(out + 13000000 + p, jp);
}

// Reduce replicas, apply grid ops, publish paired velocities, re-zero g_node.
__global__ void k_grid() {
    int n = blockIdx.x * blockDim.x + threadIdx.x;
    if (n >= N_NODES) return;
    int i = n >> 7;
    int j = n & 127;
    const float DT = 1e-4f;

    float vx = 0.f, vy = 0.f, mm = 0.f;
    const float4 z = make_float4(0.f, 0.f, 0.f, 0.f);
    #pragma unroll
    for (int r = 0; r < NREP; r++) {
        float4 nd = g_node[r][n];
        vx += nd.x; vy += nd.y; mm += nd.z;
        g_node[r][n] = z;
    }
    if (mm > 0.0f) {
        vx /= mm;
        vy /= mm;
        vy += -DT * 50.0f;
    }
    if (i < 3)    vx = fmaxf(vx, 0.0f);
    if (i >= 126) vx = fminf(vx, 0.0f);
    if (j < 3)    vy = fmaxf(vy, 0.0f);
    if (j >= 126) vy = fminf(vy, 0.0f);

    // g_pair[n] = {v[n], v[n+1]} — each thread writes its value into two pairs
    float2* gp = (float2*)g_pair;
    gp[2 * n] = make_float2(vx, vy);            // pair[n].xy = v[n]
    if (n > 0) gp[2 * n - 1] = make_float2(vx, vy);  // pair[n-1].zw = v[n]
}

__global__ void __launch_bounds__(256) k_g2p(
    const float2* __restrict__ x, float* __restrict__ out)
{
    int p = blockIdx.x * blockDim.x + threadIdx.x;
    if (p >= N_PART) return;

    const float DT = 1e-4f;
    const float INV_DX = 128.0f;
    const float DX = 1.0f / 128.0f;

    float2 xp = x[p];
    float bxf = floorf(xp.x * INV_DX - 0.5f);
    float byf = floorf(xp.y * INV_DX - 0.5f);
    int bx = (int)bxf, by = (int)byf;
    float fxx = xp.x * INV_DX - bxf;
    float fxy = xp.y * INV_DX - byf;
    float wx[3], wy[3];
    wx[0] = 0.5f * (1.5f - fxx) * (1.5f - fxx);
    wx[1] = 0.75f - (fxx - 1.0f) * (fxx - 1.0f);
    wx[2] = 0.5f * (fxx - 0.5f) * (fxx - 0.5f);
    wy[0] = 0.5f * (1.5f - fxy) * (1.5f - fxy);
    wy[1] = 0.75f - (fxy - 1.0f) * (fxy - 1.0f);
    wy[2] = 0.5f * (fxy - 0.5f) * (fxy - 0.5f);

    int j0 = by & ~1;         // aligned pair start
    int off = by - j0;        // 0 or 1

    float nvx = 0.f, nvy = 0.f;
    float b00 = 0.f, b01 = 0.f, b10 = 0.f, b11 = 0.f;

    #pragma unroll
    for (int i = 0; i < 3; i++) {
        float nodex = (float)(bx + i) * DX;
        int rowbase = (bx + i) * N_GRID;
        // two aligned 16B loads cover v[j0..j0+3]
        float4 q0 = g_pair[rowbase + j0];
        float4 q1 = g_pair[rowbase + j0 + 2];
        float gx[3], gy[3];
        if (off == 0) {
            gx[0] = q0.x; gy[0] = q0.y;
            gx[1] = q0.z; gy[1] = q0.w;
            gx[2] = q1.x; gy[2] = q1.y;
        } else {
            gx[0] = q0.z; gy[0] = q0.w;
            gx[1] = q1.x; gy[1] = q1.y;
            gx[2] = q1.z; gy[2] = q1.w;
        }
        #pragma unroll
        for (int j = 0; j < 3; j++) {
            float wt = wx[i] * wy[j];
            float nodey = (float)(by + j) * DX;
            nvx += wt * gx[j];
            nvy += wt * gy[j];
            b00 += wt * gx[j] * nodex;
            b01 += wt * gx[j] * nodey;
            b10 += wt * gy[j] * nodex;
            b11 += wt * gy[j] * nodey;
        }
    }

    const float k4 = 65536.0f;  // 4 * INV_DX^2
    float C00 = (b00 - nvx * xp.x) * k4;
    float C01 = (b01 - nvx * xp.y) * k4;
    float C10 = (b10 - nvy * xp.x) * k4;
    float C11 = (b11 - nvy * xp.y) * k4;

    __stcs((float2*)out + p, make_float2(xp.x + DT * nvx, xp.y + DT * nvy));
    __stcs((float2*)(out + 2000000) + p, make_float2(nvx, nvy));
    __stcs((float4*)(out + 4000000) + p, make_float4(C00, C01, C10, C11));
}

extern "C" void kernel_launch(void* const* d_in, const int* in_sizes, int n_in,
                              void* d_out, int out_size) {
    const float2* x  = (const float2*)d_in[0];
    const float2* v  = (const float2*)d_in[1];
    const float4* C  = (const float4*)d_in[2];
    const float4* F  = (const float4*)d_in[3];
    const int* mat   = (const int*)d_in[4];
    const float* Jp  = (const float*)d_in[5];
    float* out = (float*)d_out;

    k_p2g<<<(N_PART + 255) / 256, 256>>>(x, v, C, F, mat, Jp, out);
    k_grid<<<(N_NODES + 255) / 256, 256>>>();
    k_g2p<<<(N_PART + 255) / 256, 256>>>(x, out);
}

// round 12
// speedup vs baseline: 1.0806x; 1.0806x over previous
#include <cuda_runtime.h>
#include <cuda_bf16.h>

#define N_PART 1000000
#define N_GRID 128
#define N_NODES (N_GRID * N_GRID)
#define NREP 32

// Grid scratch (device globals — no allocation allowed; zero-initialized at load)
__device__ __align__(16) float4 g_node[NREP][N_NODES];  // (momx, momy, mass, pad)
__device__ float2 g_gv[N_NODES];   // final grid velocity for G2P

__global__ void __launch_bounds__(256) k_p2g(
    const float2* __restrict__ x, const float2* __restrict__ v,
    const float4* __restrict__ C, const float4* __restrict__ F,
    const int* __restrict__ material, const float* __restrict__ Jp,
    float* __restrict__ out)
{
    int p = blockIdx.x * blockDim.x + threadIdx.x;
    if (p >= N_PART) return;
    float4* __restrict__ rep = g_node[blockIdx.x & (NREP - 1)];

    const float DT = 1e-4f;
    const float INV_DX = 128.0f;
    const float DX = 1.0f / 128.0f;
    const float P_MASS = 1.52587890625e-05f;
    const float MU_0 = 1000.0f / (2.0f * 1.2f);
    const float LAM_0 = 1000.0f * 0.2f / (1.2f * 0.6f);

    float2 xp = x[p];
    float2 vp = v[p];
    float4 c = C[p];
    float4 f = F[p];
    int m = material[p];
    float jp = Jp[p];

    // F = F + DT * (C @ F)
    float f00 = f.x + DT * (c.x * f.x + c.y * f.z);
    float f01 = f.y + DT * (c.x * f.y + c.y * f.w);
    float f10 = f.z + DT * (c.z * f.x + c.w * f.z);
    float f11 = f.w + DT * (c.z * f.y + c.w * f.w);

    float h = (m == 1) ? 0.3f : expf(10.0f * (1.0f - jp));
    float mu = (m == 0) ? 0.0f : MU_0 * h;
    float lam = LAM_0 * h;

    // Singular values (algebraic)
    float E  = 0.5f * (f00 + f11);
    float Fm = 0.5f * (f00 - f11);
    float G  = 0.5f * (f10 + f01);
    float H  = 0.5f * (f10 - f01);
    float q2 = E * E + H * H;
    float invQ = rsqrtf(fmaxf(q2, 1e-30f));
    float Q  = q2 * invQ;
    float Rr = sqrtf(Fm * Fm + G * G);
    float sx = Q + Rr;
    float sy = Q - Rr;

    // Polar rotation R = U Vh (trig-free)
    float rc = E * invQ;
    float rs = H * invQ;
    float r00 = rc, r01 = -rs, r10 = rs, r11 = rc;

    float clx = fminf(fmaxf(sx, 0.975f), 1.0045f);
    float cly = fminf(fmaxf(sy, 0.975f), 1.0045f);
    float J;
    if (m == 2) {
        jp *= (sx * sy) / (clx * cly);
        J = clx * cly;
        // F_snow = F @ (V diag(clx/sx, cly/sy) V^T)
        float k00 = f00 * f00 + f10 * f10;
        float k11 = f01 * f01 + f11 * f11;
        float k01 = f00 * f01 + f10 * f11;
        float d  = 0.5f * (k00 - k11);
        float rr2 = d * d + k01 * k01;
        float invr = (rr2 > 1e-24f) ? rsqrtf(rr2) : 0.0f;
        float c2 = d * invr;
        float s2 = k01 * invr;
        float rr0 = clx / sx;
        float rr1 = cly / sy;
        float avg = 0.5f * (rr0 + rr1);
        float dif = 0.5f * (rr0 - rr1);
        float m00 = avg + c2 * dif;
        float m11 = avg - c2 * dif;
        float m01 = s2 * dif;
        float nf00 = f00 * m00 + f01 * m01;
        float nf01 = f00 * m01 + f01 * m11;
        float nf10 = f10 * m00 + f11 * m01;
        float nf11 = f10 * m01 + f11 * m11;
        f00 = nf00; f01 = nf01; f10 = nf10; f11 = nf11;
    } else {
        J = sx * sy;
        if (m == 0) {
            float sj = sqrtf(J);
            f00 = sj; f01 = 0.f; f10 = 0.f; f11 = sj;
        }
    }

    // stress = -DT * (2*mu*(F-R)@F^T + I*lam*J*(J-1))
    float d00 = f00 - r00, d01 = f01 - r01;
    float d10 = f10 - r10, d11 = f11 - r11;
    float tm = 2.0f * mu;
    float diag = lam * J * (J - 1.0f);
    float s00 = tm * (d00 * f00 + d01 * f01) + diag;
    float s01 = tm * (d00 * f10 + d01 * f11);
    float s10 = tm * (d10 * f00 + d11 * f01);
    float s11 = tm * (d10 * f10 + d11 * f11) + diag;
    const float scale = -1e-4f;  // -DT
    float a00 = scale * s00 + P_MASS * c.x;
    float a01 = scale * s01 + P_MASS * c.y;
    float a10 = scale * s10 + P_MASS * c.z;
    float a11 = scale * s11 + P_MASS * c.w;

    float momx = P_MASS * vp.x - (a00 * xp.x + a01 * xp.y);
    float momy = P_MASS * vp.y - (a10 * xp.x + a11 * xp.y);

    float bxf = floorf(xp.x * INV_DX - 0.5f);
    float byf = floorf(xp.y * INV_DX - 0.5f);
    int bx = (int)bxf, by = (int)byf;
    float fxx = xp.x * INV_DX - bxf;
    float fxy = xp.y * INV_DX - byf;
    float wx[3], wy[3];
    wx[0] = 0.5f * (1.5f - fxx) * (1.5f - fxx);
    wx[1] = 0.75f - (fxx - 1.0f) * (fxx - 1.0f);
    wx[2] = 0.5f * (fxx - 0.5f) * (fxx - 0.5f);
    wy[0] = 0.5f * (1.5f - fxy) * (1.5f - fxy);
    wy[1] = 0.75f - (fxy - 1.0f) * (fxy - 1.0f);
    wy[2] = 0.5f * (fxy - 0.5f) * (fxy - 0.5f);

    // Fold affine into momentum: contrib = wt * (mom + A @ node_pos)
    #pragma unroll
    for (int i = 0; i < 3; i++) {
        float nodex = (float)(bx + i) * DX;
        float axx = a00 * nodex;
        float ayx = a10 * nodex;
        int rowbase = (bx + i) * N_GRID;
        #pragma unroll
        for (int j = 0; j < 3; j++) {
            float nodey = (float)(by + j) * DX;
            float wt = wx[i] * wy[j];
            int idx = rowbase + by + j;
            float cx = wt * (momx + axx + a01 * nodey);
            float cy = wt * (momy + ayx + a11 * nodey);
            atomicAdd(&rep[idx], make_float4(cx, cy, wt * P_MASS, 0.f));
        }
    }

    // Outputs (streaming stores — keep L2 for the atomic working set)
    __stcs((float4*)(out + 8000000) + p, make_float4(f00, f01, f10, f11));
    __stcs(out + 12000000 + p, (float)m);
    __stcs(out + 13000000 + p, jp);
}

__global__ void k_grid() {
    int n = blockIdx.x * blockDim.x + threadIdx.x;
    if (n >= N_NODES) return;
    int i = n >> 7;
    int j = n & 127;
    const float DT = 1e-4f;

    float vx = 0.f, vy = 0.f, mm = 0.f;
    #pragma unroll
    for (int r = 0; r < NREP; r++) {
        float4 nd = g_node[r][n];
        vx += nd.x; vy += nd.y; mm += nd.z;
    }
    if (mm > 0.0f) {
        vx /= mm;
        vy /= mm;
        vy += -DT * 50.0f;
    }
    if (i < 3)    vx = fmaxf(vx, 0.0f);
    if (i >= 126) vx = fminf(vx, 0.0f);
    if (j < 3)    vy = fmaxf(vy, 0.0f);
    if (j >= 126) vy = fminf(vy, 0.0f);
    g_gv[n] = make_float2(vx, vy);
}

__global__ void __launch_bounds__(256) k_g2p(
    const float2* __restrict__ x, float* __restrict__ out)
{
    int p = blockIdx.x * blockDim.x + threadIdx.x;
    if (p >= N_PART) return;

    const float DT = 1e-4f;
    const float INV_DX = 128.0f;
    const float DX = 1.0f / 128.0f;

    float2 xp = x[p];
    float bxf = floorf(xp.x * INV_DX - 0.5f);
    float byf = floorf(xp.y * INV_DX - 0.5f);
    int bx = (int)bxf, by = (int)byf;
    float fxx = xp.x * INV_DX - bxf;
    float fxy = xp.y * INV_DX - byf;
    float wx[3], wy[3];
    wx[0] = 0.5f * (1.5f - fxx) * (1.5f - fxx);
    wx[1] = 0.75f - (fxx - 1.0f) * (fxx - 1.0f);
    wx[2] = 0.5f * (fxx - 0.5f) * (fxx - 0.5f);
    wy[0] = 0.5f * (1.5f - fxy) * (1.5f - fxy);
    wy[1] = 0.75f - (fxy - 1.0f) * (fxy - 1.0f);
    wy[2] = 0.5f * (fxy - 0.5f) * (fxy - 0.5f);

    float nvx = 0.f, nvy = 0.f;
    float b00 = 0.f, b01 = 0.f, b10 = 0.f, b11 = 0.f;

    #pragma unroll
    for (int i = 0; i < 3; i++) {
        float nodex = (float)(bx + i) * DX;
        #pragma unroll
        for (int j = 0; j < 3; j++) {
            float wt = wx[i] * wy[j];
            int idx = (bx + i) * N_GRID + (by + j);
            float2 gv = g_gv[idx];
            float nodey = (float)(by + j) * DX;
            nvx += wt * gv.x;
            nvy += wt * gv.y;
            b00 += wt * gv.x * nodex;
            b01 += wt * gv.x * nodey;
            b10 += wt * gv.y * nodex;
            b11 += wt * gv.y * nodey;
        }
    }

    const float k4 = 65536.0f;  // 4 * INV_DX^2
    float C00 = (b00 - nvx * xp.x) * k4;
    float C01 = (b01 - nvx * xp.y) * k4;
    float C10 = (b10 - nvy * xp.x) * k4;
    float C11 = (b11 - nvy * xp.y) * k4;

    __stcs((float2*)out + p, make_float2(xp.x + DT * nvx, xp.y + DT * nvy));
    __stcs((float2*)(out + 2000000) + p, make_float2(nvx, nvy));
    __stcs((float4*)(out + 4000000) + p, make_float4(C00, C01, C10, C11));

    // Fused re-zero of g_node for the next replay (runs last in the graph,
    // keeps accumulator lines warm in L2 for the next p2g atomic storm).
    if (p < N_NODES * NREP) {
        ((float4*)g_node)[p] = make_float4(0.f, 0.f, 0.f, 0.f);
    }
}

extern "C" void kernel_launch(void* const* d_in, const int* in_sizes, int n_in,
                              void* d_out, int out_size) {
    const float2* x  = (const float2*)d_in[0];
    const float2* v  = (const float2*)d_in[1];
    const float4* C  = (const float4*)d_in[2];
    const float4* F  = (const float4*)d_in[3];
    const int* mat   = (const int*)d_in[4];
    const float* Jp  = (const float*)d_in[5];
    float* out = (float*)d_out;

    k_p2g<<<(N_PART + 255) / 256, 256>>>(x, v, C, F, mat, Jp, out);
    k_grid<<<(N_NODES + 255) / 256, 256>>>();
    k_g2p<<<(N_PART + 255) / 256, 256>>>(x, out);
}

// round 13
// speedup vs baseline: 1.0950x; 1.0133x over previous
#include <cuda_runtime.h>
#include <cuda_bf16.h>

#define N_PART 1000000
#define N_GRID 128
#define N_NODES (N_GRID * N_GRID)
#define NREP 32

// y-swizzle so j-adjacent nodes land in different 128B L2 lines (41*25 = 1 mod 128)
__device__ __forceinline__ int swz(int y) { return (y * 41) & 127; }
__device__ __forceinline__ int unswz(int y) { return (y * 25) & 127; }

// Grid scratch (device globals — no allocation allowed; zero-initialized at load)
__device__ __align__(16) float4 g_node[NREP][N_NODES];  // swizzled-y storage
__device__ float2 g_gv[N_NODES];   // final grid velocity, logical layout

__global__ void __launch_bounds__(256) k_p2g(
    const float2* __restrict__ x, const float2* __restrict__ v,
    const float4* __restrict__ C, const float4* __restrict__ F,
    const int* __restrict__ material, const float* __restrict__ Jp,
    float* __restrict__ out)
{
    int p = blockIdx.x * blockDim.x + threadIdx.x;
    if (p >= N_PART) return;
    float4* __restrict__ rep = g_node[blockIdx.x & (NREP - 1)];

    const float DT = 1e-4f;
    const float INV_DX = 128.0f;
    const float DX = 1.0f / 128.0f;
    const float P_MASS = 1.52587890625e-05f;
    const float MU_0 = 1000.0f / (2.0f * 1.2f);
    const float LAM_0 = 1000.0f * 0.2f / (1.2f * 0.6f);

    float2 xp = x[p];
    float2 vp = v[p];
    float4 c = C[p];
    float4 f = F[p];
    int m = material[p];
    float jp = Jp[p];

    // F = F + DT * (C @ F)
    float f00 = f.x + DT * (c.x * f.x + c.y * f.z);
    float f01 = f.y + DT * (c.x * f.y + c.y * f.w);
    float f10 = f.z + DT * (c.z * f.x + c.w * f.z);
    float f11 = f.w + DT * (c.z * f.y + c.w * f.w);

    float h = (m == 1) ? 0.3f : expf(10.0f * (1.0f - jp));
    float mu = (m == 0) ? 0.0f : MU_0 * h;
    float lam = LAM_0 * h;

    // Singular values (algebraic)
    float E  = 0.5f * (f00 + f11);
    float Fm = 0.5f * (f00 - f11);
    float G  = 0.5f * (f10 + f01);
    float H  = 0.5f * (f10 - f01);
    float q2 = E * E + H * H;
    float invQ = rsqrtf(fmaxf(q2, 1e-30f));
    float Q  = q2 * invQ;
    float Rr = sqrtf(Fm * Fm + G * G);
    float sx = Q + Rr;
    float sy = Q - Rr;

    // Polar rotation R = U Vh (trig-free)
    float rc = E * invQ;
    float rs = H * invQ;
    float r00 = rc, r01 = -rs, r10 = rs, r11 = rc;

    float clx = fminf(fmaxf(sx, 0.975f), 1.0045f);
    float cly = fminf(fmaxf(sy, 0.975f), 1.0045f);
    float J;
    if (m == 2) {
        jp *= (sx * sy) / (clx * cly);
        J = clx * cly;
        // F_snow = F @ (V diag(clx/sx, cly/sy) V^T)
        float k00 = f00 * f00 + f10 * f10;
        float k11 = f01 * f01 + f11 * f11;
        float k01 = f00 * f01 + f10 * f11;
        float d  = 0.5f * (k00 - k11);
        float rr2 = d * d + k01 * k01;
        float invr = (rr2 > 1e-24f) ? rsqrtf(rr2) : 0.0f;
        float c2 = d * invr;
        float s2 = k01 * invr;
        float rr0 = clx / sx;
        float rr1 = cly / sy;
        float avg = 0.5f * (rr0 + rr1);
        float dif = 0.5f * (rr0 - rr1);
        float m00 = avg + c2 * dif;
        float m11 = avg - c2 * dif;
        float m01 = s2 * dif;
        float nf00 = f00 * m00 + f01 * m01;
        float nf01 = f00 * m01 + f01 * m11;
        float nf10 = f10 * m00 + f11 * m01;
        float nf11 = f10 * m01 + f11 * m11;
        f00 = nf00; f01 = nf01; f10 = nf10; f11 = nf11;
    } else {
        J = sx * sy;
        if (m == 0) {
            float sj = sqrtf(J);
            f00 = sj; f01 = 0.f; f10 = 0.f; f11 = sj;
        }
    }

    // stress = -DT * (2*mu*(F-R)@F^T + I*lam*J*(J-1))
    float d00 = f00 - r00, d01 = f01 - r01;
    float d10 = f10 - r10, d11 = f11 - r11;
    float tm = 2.0f * mu;
    float diag = lam * J * (J - 1.0f);
    float s00 = tm * (d00 * f00 + d01 * f01) + diag;
    float s01 = tm * (d00 * f10 + d01 * f11);
    float s10 = tm * (d10 * f00 + d11 * f01);
    float s11 = tm * (d10 * f10 + d11 * f11) + diag;
    const float scale = -1e-4f;  // -DT
    float a00 = scale * s00 + P_MASS * c.x;
    float a01 = scale * s01 + P_MASS * c.y;
    float a10 = scale * s10 + P_MASS * c.z;
    float a11 = scale * s11 + P_MASS * c.w;

    float momx = P_MASS * vp.x - (a00 * xp.x + a01 * xp.y);
    float momy = P_MASS * vp.y - (a10 * xp.x + a11 * xp.y);

    float bxf = floorf(xp.x * INV_DX - 0.5f);
    float byf = floorf(xp.y * INV_DX - 0.5f);
    int bx = (int)bxf, by = (int)byf;
    float fxx = xp.x * INV_DX - bxf;
    float fxy = xp.y * INV_DX - byf;
    float wx[3], wy[3];
    wx[0] = 0.5f * (1.5f - fxx) * (1.5f - fxx);
    wx[1] = 0.75f - (fxx - 1.0f) * (fxx - 1.0f);
    wx[2] = 0.5f * (fxx - 0.5f) * (fxx - 0.5f);
    wy[0] = 0.5f * (1.5f - fxy) * (1.5f - fxy);
    wy[1] = 0.75f - (fxy - 1.0f) * (fxy - 1.0f);
    wy[2] = 0.5f * (fxy - 0.5f) * (fxy - 0.5f);

    // Fold affine into momentum: contrib = wt * (mom + A @ node_pos)
    #pragma unroll
    for (int i = 0; i < 3; i++) {
        float nodex = (float)(bx + i) * DX;
        float axx = a00 * nodex;
        float ayx = a10 * nodex;
        int rowbase = (bx + i) * N_GRID;
        #pragma unroll
        for (int j = 0; j < 3; j++) {
            float nodey = (float)(by + j) * DX;
            float wt = wx[i] * wy[j];
            int idx = rowbase + swz(by + j);
            float cx = wt * (momx + axx + a01 * nodey);
            float cy = wt * (momy + ayx + a11 * nodey);
            atomicAdd(&rep[idx], make_float4(cx, cy, wt * P_MASS, 0.f));
        }
    }

    // Outputs (streaming stores — keep L2 for the atomic working set)
    __stcs((float4*)(out + 8000000) + p, make_float4(f00, f01, f10, f11));
    __stcs(out + 12000000 + p, (float)m);
    __stcs(out + 13000000 + p, jp);
}

// Iterate in STORAGE order (coalesced g_node reads), recover logical j via
// the inverse swizzle, scatter-write only the small g_gv array.
__global__ void k_grid() {
    int n = blockIdx.x * blockDim.x + threadIdx.x;
    if (n >= N_NODES) return;
    int i = n >> 7;
    int js = n & 127;
    int j = unswz(js);       // logical column
    const float DT = 1e-4f;

    float vx = 0.f, vy = 0.f, mm = 0.f;
    #pragma unroll
    for (int r = 0; r < NREP; r++) {
        float4 nd = g_node[r][n];
        vx += nd.x; vy += nd.y; mm += nd.z;
    }
    if (mm > 0.0f) {
        vx /= mm;
        vy /= mm;
        vy += -DT * 50.0f;
    }
    if (i < 3)    vx = fmaxf(vx, 0.0f);
    if (i >= 126) vx = fminf(vx, 0.0f);
    if (j < 3)    vy = fmaxf(vy, 0.0f);
    if (j >= 126) vy = fminf(vy, 0.0f);
    g_gv[i * N_GRID + j] = make_float2(vx, vy);
}

__global__ void __launch_bounds__(256) k_g2p(
    const float2* __restrict__ x, float* __restrict__ out)
{
    int p = blockIdx.x * blockDim.x + threadIdx.x;
    if (p >= N_PART) return;

    const float DT = 1e-4f;
    const float INV_DX = 128.0f;
    const float DX = 1.0f / 128.0f;

    float2 xp = x[p];
    float bxf = floorf(xp.x * INV_DX - 0.5f);
    float byf = floorf(xp.y * INV_DX - 0.5f);
    int bx = (int)bxf, by = (int)byf;
    float fxx = xp.x * INV_DX - bxf;
    float fxy = xp.y * INV_DX - byf;
    float wx[3], wy[3];
    wx[0] = 0.5f * (1.5f - fxx) * (1.5f - fxx);
    wx[1] = 0.75f - (fxx - 1.0f) * (fxx - 1.0f);
    wx[2] = 0.5f * (fxx - 0.5f) * (fxx - 0.5f);
    wy[0] = 0.5f * (1.5f - fxy) * (1.5f - fxy);
    wy[1] = 0.75f - (fxy - 1.0f) * (fxy - 1.0f);
    wy[2] = 0.5f * (fxy - 0.5f) * (fxy - 0.5f);

    float nvx = 0.f, nvy = 0.f;
    float b00 = 0.f, b01 = 0.f, b10 = 0.f, b11 = 0.f;

    #pragma unroll
    for (int i = 0; i < 3; i++) {
        float nodex = (float)(bx + i) * DX;
        #pragma unroll
        for (int j = 0; j < 3; j++) {
            float wt = wx[i] * wy[j];
            int idx = (bx + i) * N_GRID + (by + j);
            float2 gv = g_gv[idx];
            float nodey = (float)(by + j) * DX;
            nvx += wt * gv.x;
            nvy += wt * gv.y;
            b00 += wt * gv.x * nodex;
            b01 += wt * gv.x * nodey;
            b10 += wt * gv.y * nodex;
            b11 += wt * gv.y * nodey;
        }
    }

    const float k4 = 65536.0f;  // 4 * INV_DX^2
    float C00 = (b00 - nvx * xp.x) * k4;
    float C01 = (b01 - nvx * xp.y) * k4;
    float C10 = (b10 - nvy * xp.x) * k4;
    float C11 = (b11 - nvy * xp.y) * k4;

    __stcs((float2*)out + p, make_float2(xp.x + DT * nvx, xp.y + DT * nvy));
    __stcs((float2*)(out + 2000000) + p, make_float2(nvx, nvy));
    __stcs((float4*)(out + 4000000) + p, make_float4(C00, C01, C10, C11));

    // Fused re-zero of g_node for the next replay (layout-agnostic).
    if (p < N_NODES * NREP) {
        ((float4*)g_node)[p] = make_float4(0.f, 0.f, 0.f, 0.f);
    }
}

extern "C" void kernel_launch(void* const* d_in, const int* in_sizes, int n_in,
                              void* d_out, int out_size) {
    const float2* x  = (const float2*)d_in[0];
    const float2* v  = (const float2*)d_in[1];
    const float4* C  = (const float4*)d_in[2];
    const float4* F  = (const float4*)d_in[3];
    const int* mat   = (const int*)d_in[4];
    const float* Jp  = (const float*)d_in[5];
    float* out = (float*)d_out;

    k_p2g<<<(N_PART + 255) / 256, 256>>>(x, v, C, F, mat, Jp, out);
    k_grid<<<(N_NODES + 255) / 256, 256>>>();
    k_g2p<<<(N_PART + 255) / 256, 256>>>(x, out);
}

// round 14
// speedup vs baseline: 1.1320x; 1.0338x over previous
#include <cuda_runtime.h>
#include <cuda_bf16.h>

#define N_PART 1000000
#define N_GRID 128
#define N_NODES (N_GRID * N_GRID)
#define NREP 32
#define G2P_BLOCKS 148
#define G2P_THREADS 1024

// y-swizzle so j-adjacent nodes land in different 128B L2 lines (41*25 = 1 mod 128)
__device__ __forceinline__ int swz(int y) { return (y * 41) & 127; }
__device__ __forceinline__ int unswz(int y) { return (y * 25) & 127; }

// Grid scratch (device globals — no allocation allowed; zero-initialized at load)
__device__ __align__(16) float4 g_node[NREP][N_NODES];  // swizzled-y storage
__device__ __align__(16) float2 g_gv[N_NODES];          // final grid velocity, logical layout

__global__ void __launch_bounds__(256) k_p2g(
    const float2* __restrict__ x, const float2* __restrict__ v,
    const float4* __restrict__ C, const float4* __restrict__ F,
    const int* __restrict__ material, const float* __restrict__ Jp,
    float* __restrict__ out)
{
    int p = blockIdx.x * blockDim.x + threadIdx.x;
    if (p >= N_PART) return;
    float4* __restrict__ rep = g_node[blockIdx.x & (NREP - 1)];

    const float DT = 1e-4f;
    const float INV_DX = 128.0f;
    const float DX = 1.0f / 128.0f;
    const float P_MASS = 1.52587890625e-05f;
    const float MU_0 = 1000.0f / (2.0f * 1.2f);
    const float LAM_0 = 1000.0f * 0.2f / (1.2f * 0.6f);

    float2 xp = x[p];
    float2 vp = v[p];
    float4 c = C[p];
    float4 f = F[p];
    int m = material[p];
    float jp = Jp[p];

    // F = F + DT * (C @ F)
    float f00 = f.x + DT * (c.x * f.x + c.y * f.z);
    float f01 = f.y + DT * (c.x * f.y + c.y * f.w);
    float f10 = f.z + DT * (c.z * f.x + c.w * f.z);
    float f11 = f.w + DT * (c.z * f.y + c.w * f.w);

    float h = (m == 1) ? 0.3f : expf(10.0f * (1.0f - jp));
    float mu = (m == 0) ? 0.0f : MU_0 * h;
    float lam = LAM_0 * h;

    // Singular values (algebraic)
    float E  = 0.5f * (f00 + f11);
    float Fm = 0.5f * (f00 - f11);
    float G  = 0.5f * (f10 + f01);
    float H  = 0.5f * (f10 - f01);
    float q2 = E * E + H * H;
    float invQ = rsqrtf(fmaxf(q2, 1e-30f));
    float Q  = q2 * invQ;
    float Rr = sqrtf(Fm * Fm + G * G);
    float sx = Q + Rr;
    float sy = Q - Rr;

    // Polar rotation R = U Vh (trig-free)
    float rc = E * invQ;
    float rs = H * invQ;
    float r00 = rc, r01 = -rs, r10 = rs, r11 = rc;

    float clx = fminf(fmaxf(sx, 0.975f), 1.0045f);
    float cly = fminf(fmaxf(sy, 0.975f), 1.0045f);
    float J;
    if (m == 2) {
        jp *= (sx * sy) / (clx * cly);
        J = clx * cly;
        // F_snow = F @ (V diag(clx/sx, cly/sy) V^T)
        float k00 = f00 * f00 + f10 * f10;
        float k11 = f01 * f01 + f11 * f11;
        float k01 = f00 * f01 + f10 * f11;
        float d  = 0.5f * (k00 - k11);
        float rr2 = d * d + k01 * k01;
        float invr = (rr2 > 1e-24f) ? rsqrtf(rr2) : 0.0f;
        float c2 = d * invr;
        float s2 = k01 * invr;
        float rr0 = clx / sx;
        float rr1 = cly / sy;
        float avg = 0.5f * (rr0 + rr1);
        float dif = 0.5f * (rr0 - rr1);
        float m00 = avg + c2 * dif;
        float m11 = avg - c2 * dif;
        float m01 = s2 * dif;
        float nf00 = f00 * m00 + f01 * m01;
        float nf01 = f00 * m01 + f01 * m11;
        float nf10 = f10 * m00 + f11 * m01;
        float nf11 = f10 * m01 + f11 * m11;
        f00 = nf00; f01 = nf01; f10 = nf10; f11 = nf11;
    } else {
        J = sx * sy;
        if (m == 0) {
            float sj = sqrtf(J);
            f00 = sj; f01 = 0.f; f10 = 0.f; f11 = sj;
        }
    }

    // stress = -DT * (2*mu*(F-R)@F^T + I*lam*J*(J-1))
    float d00 = f00 - r00, d01 = f01 - r01;
    float d10 = f10 - r10, d11 = f11 - r11;
    float tm = 2.0f * mu;
    float diag = lam * J * (J - 1.0f);
    float s00 = tm * (d00 * f00 + d01 * f01) + diag;
    float s01 = tm * (d00 * f10 + d01 * f11);
    float s10 = tm * (d10 * f00 + d11 * f01);
    float s11 = tm * (d10 * f10 + d11 * f11) + diag;
    const float scale = -1e-4f;  // -DT
    float a00 = scale * s00 + P_MASS * c.x;
    float a01 = scale * s01 + P_MASS * c.y;
    float a10 = scale * s10 + P_MASS * c.z;
    float a11 = scale * s11 + P_MASS * c.w;

    float momx = P_MASS * vp.x - (a00 * xp.x + a01 * xp.y);
    float momy = P_MASS * vp.y - (a10 * xp.x + a11 * xp.y);

    float bxf = floorf(xp.x * INV_DX - 0.5f);
    float byf = floorf(xp.y * INV_DX - 0.5f);
    int bx = (int)bxf, by = (int)byf;
    float fxx = xp.x * INV_DX - bxf;
    float fxy = xp.y * INV_DX - byf;
    float wx[3], wy[3];
    wx[0] = 0.5f * (1.5f - fxx) * (1.5f - fxx);
    wx[1] = 0.75f - (fxx - 1.0f) * (fxx - 1.0f);
    wx[2] = 0.5f * (fxx - 0.5f) * (fxx - 0.5f);
    wy[0] = 0.5f * (1.5f - fxy) * (1.5f - fxy);
    wy[1] = 0.75f - (fxy - 1.0f) * (fxy - 1.0f);
    wy[2] = 0.5f * (fxy - 0.5f) * (fxy - 0.5f);

    // Fold affine into momentum: contrib = wt * (mom + A @ node_pos)
    #pragma unroll
    for (int i = 0; i < 3; i++) {
        float nodex = (float)(bx + i) * DX;
        float axx = a00 * nodex;
        float ayx = a10 * nodex;
        int rowbase = (bx + i) * N_GRID;
        #pragma unroll
        for (int j = 0; j < 3; j++) {
            float nodey = (float)(by + j) * DX;
            float wt = wx[i] * wy[j];
            int idx = rowbase + swz(by + j);
            float cx = wt * (momx + axx + a01 * nodey);
            float cy = wt * (momy + ayx + a11 * nodey);
            atomicAdd(&rep[idx], make_float4(cx, cy, wt * P_MASS, 0.f));
        }
    }

    // Outputs (streaming stores — keep L2 for the atomic working set)
    __stcs((float4*)(out + 8000000) + p, make_float4(f00, f01, f10, f11));
    __stcs(out + 12000000 + p, (float)m);
    __stcs(out + 13000000 + p, jp);
}

// Iterate in STORAGE order (coalesced g_node reads), recover logical j via
// the inverse swizzle, scatter-write only the small g_gv array.
__global__ void k_grid() {
    int n = blockIdx.x * blockDim.x + threadIdx.x;
    if (n >= N_NODES) return;
    int i = n >> 7;
    int js = n & 127;
    int j = unswz(js);       // logical column
    const float DT = 1e-4f;

    float vx = 0.f, vy = 0.f, mm = 0.f;
    #pragma unroll
    for (int r = 0; r < NREP; r++) {
        float4 nd = g_node[r][n];
        vx += nd.x; vy += nd.y; mm += nd.z;
    }
    if (mm > 0.0f) {
        vx /= mm;
        vy /= mm;
        vy += -DT * 50.0f;
    }
    if (i < 3)    vx = fmaxf(vx, 0.0f);
    if (i >= 126) vx = fminf(vx, 0.0f);
    if (j < 3)    vy = fmaxf(vy, 0.0f);
    if (j >= 126) vy = fminf(vy, 0.0f);
    g_gv[i * N_GRID + j] = make_float2(vx, vy);
}

// One block per SM; entire g_gv staged in dynamic shared memory; gathers via LDS.
__global__ void __launch_bounds__(G2P_THREADS) k_g2p(
    const float2* __restrict__ x, float* __restrict__ out)
{
    extern __shared__ float2 sgv[];
    // Cooperative stage: 128 KB, coalesced float4 loads
    {
        const float4* src = (const float4*)g_gv;
        float4* dst = (float4*)sgv;
        #pragma unroll
        for (int k = threadIdx.x; k < N_NODES / 2; k += G2P_THREADS)
            dst[k] = src[k];
    }
    __syncthreads();

    const float DT = 1e-4f;
    const float INV_DX = 128.0f;
    const float DX = 1.0f / 128.0f;

    const int chunk = (N_PART + G2P_BLOCKS - 1) / G2P_BLOCKS;  // 6757
    int base = blockIdx.x * chunk;
    int pend = min(base + chunk, N_PART);

    for (int p = base + threadIdx.x; p < pend; p += G2P_THREADS) {
        float2 xp = x[p];
        float bxf = floorf(xp.x * INV_DX - 0.5f);
        float byf = floorf(xp.y * INV_DX - 0.5f);
        int bx = (int)bxf, by = (int)byf;
        float fxx = xp.x * INV_DX - bxf;
        float fxy = xp.y * INV_DX - byf;
        float wx[3], wy[3];
        wx[0] = 0.5f * (1.5f - fxx) * (1.5f - fxx);
        wx[1] = 0.75f - (fxx - 1.0f) * (fxx - 1.0f);
        wx[2] = 0.5f * (fxx - 0.5f) * (fxx - 0.5f);
        wy[0] = 0.5f * (1.5f - fxy) * (1.5f - fxy);
        wy[1] = 0.75f - (fxy - 1.0f) * (fxy - 1.0f);
        wy[2] = 0.5f * (fxy - 0.5f) * (fxy - 0.5f);

        float nvx = 0.f, nvy = 0.f;
        float b00 = 0.f, b01 = 0.f, b10 = 0.f, b11 = 0.f;

        #pragma unroll
        for (int i = 0; i < 3; i++) {
            float nodex = (float)(bx + i) * DX;
            int rowbase = (bx + i) * N_GRID;
            #pragma unroll
            for (int j = 0; j < 3; j++) {
                float wt = wx[i] * wy[j];
                float2 gv = sgv[rowbase + by + j];
                float nodey = (float)(by + j) * DX;
                nvx += wt * gv.x;
                nvy += wt * gv.y;
                b00 += wt * gv.x * nodex;
                b01 += wt * gv.x * nodey;
                b10 += wt * gv.y * nodex;
                b11 += wt * gv.y * nodey;
            }
        }

        const float k4 = 65536.0f;  // 4 * INV_DX^2
        float C00 = (b00 - nvx * xp.x) * k4;
        float C01 = (b01 - nvx * xp.y) * k4;
        float C10 = (b10 - nvy * xp.x) * k4;
        float C11 = (b11 - nvy * xp.y) * k4;

        __stcs((float2*)out + p, make_float2(xp.x + DT * nvx, xp.y + DT * nvy));
        __stcs((float2*)(out + 2000000) + p, make_float2(nvx, nvy));
        __stcs((float4*)(out + 4000000) + p, make_float4(C00, C01, C10, C11));
    }

    // Fused re-zero of g_node for the next replay (grid-strided).
    const float4 z = make_float4(0.f, 0.f, 0.f, 0.f);
    int total4 = N_NODES * NREP;
    for (int k = blockIdx.x * G2P_THREADS + threadIdx.x; k < total4;
         k += G2P_BLOCKS * G2P_THREADS)
        ((float4*)g_node)[k] = z;
}

extern "C" void kernel_launch(void* const* d_in, const int* in_sizes, int n_in,
                              void* d_out, int out_size) {
    const float2* x  = (const float2*)d_in[0];
    const float2* v  = (const float2*)d_in[1];
    const float4* C  = (const float4*)d_in[2];
    const float4* F  = (const float4*)d_in[3];
    const int* mat   = (const int*)d_in[4];
    const float* Jp  = (const float*)d_in[5];
    float* out = (float*)d_out;

    static bool attr_done = false;
    if (!attr_done) {
        cudaFuncSetAttribute(k_g2p, cudaFuncAttributeMaxDynamicSharedMemorySize,
                             N_NODES * (int)sizeof(float2));
        attr_done = true;
    }

    k_p2g<<<(N_PART + 255) / 256, 256>>>(x, v, C, F, mat, Jp, out);
    k_grid<<<(N_NODES + 255) / 256, 256>>>();
    k_g2p<<<G2P_BLOCKS, G2P_THREADS, N_NODES * sizeof(float2)>>>(x, out);
}

// round 15
// speedup vs baseline: 1.1649x; 1.0291x over previous
#include <cuda_runtime.h>
#include <cuda_bf16.h>

#define N_PART 1000000
#define N_GRID 128
#define N_NODES (N_GRID * N_GRID)
#define NREP 16
#define G2P_BLOCKS 148
#define G2P_THREADS 1024

// y-swizzle so j-adjacent nodes land in different 128B L2 lines (41*25 = 1 mod 128)
__device__ __forceinline__ int swz(int y) { return (y * 41) & 127; }
__device__ __forceinline__ int unswz(int y) { return (y * 25) & 127; }

// Grid scratch (device globals — no allocation allowed; zero-initialized at load)
__device__ __align__(16) float4 g_node[NREP][N_NODES];  // swizzled-y storage
__device__ __align__(16) float2 g_gv[N_NODES];          // final grid velocity, logical layout

__global__ void __launch_bounds__(256) k_p2g(
    const float2* __restrict__ x, const float2* __restrict__ v,
    const float4* __restrict__ C, const float4* __restrict__ F,
    const int* __restrict__ material, const float* __restrict__ Jp,
    float* __restrict__ out)
{
    int p = blockIdx.x * blockDim.x + threadIdx.x;
    if (p >= N_PART) return;
    float4* __restrict__ rep = g_node[blockIdx.x & (NREP - 1)];

    const float DT = 1e-4f;
    const float INV_DX = 128.0f;
    const float DX = 1.0f / 128.0f;
    const float P_MASS = 1.52587890625e-05f;
    const float MU_0 = 1000.0f / (2.0f * 1.2f);
    const float LAM_0 = 1000.0f * 0.2f / (1.2f * 0.6f);

    float2 xp = x[p];
    float2 vp = v[p];
    float4 c = C[p];
    float4 f = F[p];
    int m = material[p];
    float jp = Jp[p];

    // F = F + DT * (C @ F)
    float f00 = f.x + DT * (c.x * f.x + c.y * f.z);
    float f01 = f.y + DT * (c.x * f.y + c.y * f.w);
    float f10 = f.z + DT * (c.z * f.x + c.w * f.z);
    float f11 = f.w + DT * (c.z * f.y + c.w * f.w);

    float h = (m == 1) ? 0.3f : expf(10.0f * (1.0f - jp));
    float mu = (m == 0) ? 0.0f : MU_0 * h;
    float lam = LAM_0 * h;

    // Singular values (algebraic)
    float E  = 0.5f * (f00 + f11);
    float Fm = 0.5f * (f00 - f11);
    float G  = 0.5f * (f10 + f01);
    float H  = 0.5f * (f10 - f01);
    float q2 = E * E + H * H;
    float invQ = rsqrtf(fmaxf(q2, 1e-30f));
    float Q  = q2 * invQ;
    float Rr = sqrtf(Fm * Fm + G * G);
    float sx = Q + Rr;
    float sy = Q - Rr;

    // Polar rotation R = U Vh (trig-free)
    float rc = E * invQ;
    float rs = H * invQ;
    float r00 = rc, r01 = -rs, r10 = rs, r11 = rc;

    float clx = fminf(fmaxf(sx, 0.975f), 1.0045f);
    float cly = fminf(fmaxf(sy, 0.975f), 1.0045f);
    float J;
    if (m == 2) {
        jp *= (sx * sy) / (clx * cly);
        J = clx * cly;
        // F_snow = F @ (V diag(clx/sx, cly/sy) V^T)
        float k00 = f00 * f00 + f10 * f10;
        float k11 = f01 * f01 + f11 * f11;
        float k01 = f00 * f01 + f10 * f11;
        float d  = 0.5f * (k00 - k11);
        float rr2 = d * d + k01 * k01;
        float invr = (rr2 > 1e-24f) ? rsqrtf(rr2) : 0.0f;
        float c2 = d * invr;
        float s2 = k01 * invr;
        float rr0 = clx / sx;
        float rr1 = cly / sy;
        float avg = 0.5f * (rr0 + rr1);
        float dif = 0.5f * (rr0 - rr1);
        float m00 = avg + c2 * dif;
        float m11 = avg - c2 * dif;
        float m01 = s2 * dif;
        float nf00 = f00 * m00 + f01 * m01;
        float nf01 = f00 * m01 + f01 * m11;
        float nf10 = f10 * m00 + f11 * m01;
        float nf11 = f10 * m01 + f11 * m11;
        f00 = nf00; f01 = nf01; f10 = nf10; f11 = nf11;
    } else {
        J = sx * sy;
        if (m == 0) {
            float sj = sqrtf(J);
            f00 = sj; f01 = 0.f; f10 = 0.f; f11 = sj;
        }
    }

    // stress = -DT * (2*mu*(F-R)@F^T + I*lam*J*(J-1))
    float d00 = f00 - r00, d01 = f01 - r01;
    float d10 = f10 - r10, d11 = f11 - r11;
    float tm = 2.0f * mu;
    float diag = lam * J * (J - 1.0f);
    float s00 = tm * (d00 * f00 + d01 * f01) + diag;
    float s01 = tm * (d00 * f10 + d01 * f11);
    float s10 = tm * (d10 * f00 + d11 * f01);
    float s11 = tm * (d10 * f10 + d11 * f11) + diag;
    const float scale = -1e-4f;  // -DT
    float a00 = scale * s00 + P_MASS * c.x;
    float a01 = scale * s01 + P_MASS * c.y;
    float a10 = scale * s10 + P_MASS * c.z;
    float a11 = scale * s11 + P_MASS * c.w;

    float momx = P_MASS * vp.x - (a00 * xp.x + a01 * xp.y);
    float momy = P_MASS * vp.y - (a10 * xp.x + a11 * xp.y);

    float bxf = floorf(xp.x * INV_DX - 0.5f);
    float byf = floorf(xp.y * INV_DX - 0.5f);
    int bx = (int)bxf, by = (int)byf;
    float fxx = xp.x * INV_DX - bxf;
    float fxy = xp.y * INV_DX - byf;
    float wx[3], wy[3];
    wx[0] = 0.5f * (1.5f - fxx) * (1.5f - fxx);
    wx[1] = 0.75f - (fxx - 1.0f) * (fxx - 1.0f);
    wx[2] = 0.5f * (fxx - 0.5f) * (fxx - 0.5f);
    wy[0] = 0.5f * (1.5f - fxy) * (1.5f - fxy);
    wy[1] = 0.75f - (fxy - 1.0f) * (fxy - 1.0f);
    wy[2] = 0.5f * (fxy - 0.5f) * (fxy - 0.5f);

    // Outputs (streaming stores — keep L2 for the atomic working set)
    __stcs((float4*)(out + 8000000) + p, make_float4(f00, f01, f10, f11));
    __stcs(out + 12000000 + p, (float)m);
    __stcs(out + 13000000 + p, jp);

    // Fold affine into momentum: contrib = wt * (mom + A @ node_pos)
    #pragma unroll
    for (int i = 0; i < 3; i++) {
        float nodex = (float)(bx + i) * DX;
        float axx = a00 * nodex;
        float ayx = a10 * nodex;
        int rowbase = (bx + i) * N_GRID;
        #pragma unroll
        for (int j = 0; j < 3; j++) {
            float nodey = (float)(by + j) * DX;
            float wt = wx[i] * wy[j];
            int idx = rowbase + swz(by + j);
            float cx = wt * (momx + axx + a01 * nodey);
            float cy = wt * (momy + ayx + a11 * nodey);
            atomicAdd(&rep[idx], make_float4(cx, cy, wt * P_MASS, 0.f));
        }
    }
}

// Iterate in STORAGE order (coalesced g_node reads), recover logical j via
// the inverse swizzle, scatter-write only the small g_gv array.
__global__ void k_grid() {
    int n = blockIdx.x * blockDim.x + threadIdx.x;
    if (n >= N_NODES) return;
    int i = n >> 7;
    int js = n & 127;
    int j = unswz(js);       // logical column
    const float DT = 1e-4f;

    float vx = 0.f, vy = 0.f, mm = 0.f;
    #pragma unroll
    for (int r = 0; r < NREP; r++) {
        float4 nd = g_node[r][n];
        vx += nd.x; vy += nd.y; mm += nd.z;
    }
    if (mm > 0.0f) {
        vx /= mm;
        vy /= mm;
        vy += -DT * 50.0f;
    }
    if (i < 3)    vx = fmaxf(vx, 0.0f);
    if (i >= 126) vx = fminf(vx, 0.0f);
    if (j < 3)    vy = fmaxf(vy, 0.0f);
    if (j >= 126) vy = fminf(vy, 0.0f);
    g_gv[i * N_GRID + j] = make_float2(vx, vy);
}

// One block per SM; entire g_gv staged in shared memory; 2 particles/thread
// with vectorized loads/stores; fused g_node re-zero at the tail.
__global__ void __launch_bounds__(G2P_THREADS) k_g2p(
    const float2* __restrict__ x, float* __restrict__ out)
{
    extern __shared__ float2 sgv[];
    {
        const float4* src = (const float4*)g_gv;
        float4* dst = (float4*)sgv;
        #pragma unroll
        for (int k = threadIdx.x; k < N_NODES / 2; k += G2P_THREADS)
            dst[k] = src[k];
    }
    __syncthreads();

    const float DT = 1e-4f;
    const float INV_DX = 128.0f;
    const float DX = 1.0f / 128.0f;

    const int chunk = 6760;  // even, 148*6760 >= 1M
    int base = blockIdx.x * chunk;
    int pend = min(base + chunk, N_PART);

    for (int p = base + 2 * threadIdx.x; p < pend; p += 2 * G2P_THREADS) {
        // p is even; pair (p, p+1) both < pend (chunk and N_PART even)
        float4 xq = ((const float4*)x)[p >> 1];

        float nv_[2][2];
        float Cv[2][4];
        #pragma unroll
        for (int u = 0; u < 2; u++) {
            float xpx = (u == 0) ? xq.x : xq.z;
            float xpy = (u == 0) ? xq.y : xq.w;
            float bxf = floorf(xpx * INV_DX - 0.5f);
            float byf = floorf(xpy * INV_DX - 0.5f);
            int bx = (int)bxf, by = (int)byf;
            float fxx = xpx * INV_DX - bxf;
            float fxy = xpy * INV_DX - byf;
            float wx[3], wy[3];
            wx[0] = 0.5f * (1.5f - fxx) * (1.5f - fxx);
            wx[1] = 0.75f - (fxx - 1.0f) * (fxx - 1.0f);
            wx[2] = 0.5f * (fxx - 0.5f) * (fxx - 0.5f);
            wy[0] = 0.5f * (1.5f - fxy) * (1.5f - fxy);
            wy[1] = 0.75f - (fxy - 1.0f) * (fxy - 1.0f);
            wy[2] = 0.5f * (fxy - 0.5f) * (fxy - 0.5f);

            float nvx = 0.f, nvy = 0.f;
            float b00 = 0.f, b01 = 0.f, b10 = 0.f, b11 = 0.f;
            #pragma unroll
            for (int i = 0; i < 3; i++) {
                float nodex = (float)(bx + i) * DX;
                int rowbase = (bx + i) * N_GRID;
                #pragma unroll
                for (int j = 0; j < 3; j++) {
                    float wt = wx[i] * wy[j];
                    float2 gv = sgv[rowbase + by + j];
                    float nodey = (float)(by + j) * DX;
                    nvx += wt * gv.x;
                    nvy += wt * gv.y;
                    b00 += wt * gv.x * nodex;
                    b01 += wt * gv.x * nodey;
                    b10 += wt * gv.y * nodex;
                    b11 += wt * gv.y * nodey;
                }
            }
            const float k4 = 65536.0f;  // 4 * INV_DX^2
            nv_[u][0] = nvx; nv_[u][1] = nvy;
            Cv[u][0] = (b00 - nvx * xpx) * k4;
            Cv[u][1] = (b01 - nvx * xpy) * k4;
            Cv[u][2] = (b10 - nvy * xpx) * k4;
            Cv[u][3] = (b11 - nvy * xpy) * k4;
        }

        // vectorized pair stores
        __stcs((float4*)out + (p >> 1),
               make_float4(xq.x + DT * nv_[0][0], xq.y + DT * nv_[0][1],
                           xq.z + DT * nv_[1][0], xq.w + DT * nv_[1][1]));
        __stcs((float4*)(out + 2000000) + (p >> 1),
               make_float4(nv_[0][0], nv_[0][1], nv_[1][0], nv_[1][1]));
        __stcs((float4*)(out + 4000000) + p,
               make_float4(Cv[0][0], Cv[0][1], Cv[0][2], Cv[0][3]));
        __stcs((float4*)(out + 4000000) + p + 1,
               make_float4(Cv[1][0], Cv[1][1], Cv[1][2], Cv[1][3]));
    }

    // Fused re-zero of g_node for the next replay (grid-strided).
    const float4 z = make_float4(0.f, 0.f, 0.f, 0.f);
    int total4 = N_NODES * NREP;
    for (int k = blockIdx.x * G2P_THREADS + threadIdx.x; k < total4;
         k += G2P_BLOCKS * G2P_THREADS)
        ((float4*)g_node)[k] = z;
}

extern "C" void kernel_launch(void* const* d_in, const int* in_sizes, int n_in,
                              void* d_out, int out_size) {
    const float2* x  = (const float2*)d_in[0];
    const float2* v  = (const float2*)d_in[1];
    const float4* C  = (const float4*)d_in[2];
    const float4* F  = (const float4*)d_in[3];
    const int* mat   = (const int*)d_in[4];
    const float* Jp  = (const float*)d_in[5];
    float* out = (float*)d_out;

    static bool attr_done = false;
    if (!attr_done) {
        cudaFuncSetAttribute(k_g2p, cudaFuncAttributeMaxDynamicSharedMemorySize,
                             N_NODES * (int)sizeof(float2));
        attr_done = true;
    }

    k_p2g<<<(N_PART + 255) / 256, 256>>>(x, v, C, F, mat, Jp, out);
    k_grid<<<(N_NODES + 255) / 256, 256>>>();
    k_g2p<<<G2P_BLOCKS, G2P_THREADS, N_NODES * sizeof(float2)>>>(x, out);
}